// round 4
// baseline (speedup 1.0000x reference)
#include <cuda_runtime.h>

#define B_    32
#define SPAST 4095
#define SEQ   4096
#define H_    2048
#define NH_   16
#define HD_   128

// Scratch (no allocations allowed) -----------------------------------------
__device__ float g_qkv_part[8 * B_ * 3 * H_];   // QKV k-split partials
__device__ float g_qkv[B_ * 3 * H_];            // reduced qkv [32][6144]
__device__ float g_ctx[B_ * H_];                // attention output [32][2048]
__device__ float g_out_part[16 * B_ * H_];      // proj k-split partials

// ---------------------------------------------------------------------------
// Skinny GEMM: P[ks][b][n] = sum_{k in segment ks} X[b][k] * W[k][n]
// X: [32][2048] row-major, W: [2048][N] row-major.
// Block = 128 threads, tile 32b x 128n, thread tile 8b x 4n.
// ---------------------------------------------------------------------------
__global__ __launch_bounds__(128) void gemm32_kernel(
    const float* __restrict__ X, const float* __restrict__ W,
    float* __restrict__ P, int N, int kseg) {
  const int t = threadIdx.x;
  const int ng = t & 31;        // n-group 0..31 (4 cols each)
  const int bg = t >> 5;        // b-group 0..3  (8 rows each)
  const int n0 = blockIdx.x * 128 + ng * 4;
  const int kbeg = blockIdx.y * kseg;

  __shared__ float xs[32][33];  // [b][kk], padded: conflict-free stage + bcast read
  float acc[8][4];
#pragma unroll
  for (int i = 0; i < 8; i++)
#pragma unroll
    for (int j = 0; j < 4; j++) acc[i][j] = 0.f;

  for (int kc = 0; kc < kseg; kc += 32) {
    __syncthreads();
#pragma unroll
    for (int i = t; i < 1024; i += 128) {
      int bb = i >> 5, kk = i & 31;                 // coalesced gmem, clean smem banks
      xs[bb][kk] = X[bb * 2048 + kbeg + kc + kk];
    }
    __syncthreads();
#pragma unroll 4
    for (int kk = 0; kk < 32; kk++) {
      float4 w4 = *reinterpret_cast<const float4*>(
          W + (size_t)(kbeg + kc + kk) * N + n0);
#pragma unroll
      for (int i = 0; i < 8; i++) {
        float xv = xs[bg * 8 + i][kk];
        acc[i][0] += xv * w4.x;
        acc[i][1] += xv * w4.y;
        acc[i][2] += xv * w4.z;
        acc[i][3] += xv * w4.w;
      }
    }
  }
  float* p = P + (size_t)blockIdx.y * 32 * N;
#pragma unroll
  for (int i = 0; i < 8; i++) {
    float4 v = make_float4(acc[i][0], acc[i][1], acc[i][2], acc[i][3]);
    *reinterpret_cast<float4*>(p + (size_t)(bg * 8 + i) * N + n0) = v;
  }
}

// out[b][n] = sum_ks P[ks][b][n] + bias[n]
__global__ void reduce_bias_kernel(const float* __restrict__ P,
                                   const float* __restrict__ bias,
                                   float* __restrict__ out, int N, int nsplit) {
  int i = blockIdx.x * 256 + threadIdx.x;
  int total = B_ * N;
  if (i >= total) return;
  float s = bias[i % N];
  for (int k = 0; k < nsplit; k++) s += P[(size_t)k * total + i];
  out[i] = s;
}

// ---------------------------------------------------------------------------
// Decode attention: one block per (b, h). 256 threads = 8 warps.
// Phase 1: scores via float4 row-dot + warp shuffle reduce (coalesced 512B/row)
// Phase 2: block softmax in smem
// Phase 3: ctx = probs @ V with 8-way s-split, smem combine
// ---------------------------------------------------------------------------
__global__ __launch_bounds__(256) void attn_kernel(
    const float* __restrict__ past_key, const float* __restrict__ past_value) {
  const int h = blockIdx.x;
  const int b = blockIdx.y;
  const int t = threadIdx.x;
  const int lane = t & 31;
  const int wid = t >> 5;

  __shared__ float q_s[HD_];
  __shared__ float sc[SEQ];       // 16 KB scores
  __shared__ float red[32];
  __shared__ float ctxp[8][HD_];  // 4 KB partial ctx

  const float* qp = g_qkv + b * (3 * H_) + h * HD_;
  if (t < HD_) q_s[t] = qp[t] * 0.08838834764831845f;  // 1/sqrt(128)
  __syncthreads();

  const float4 qv = *reinterpret_cast<const float4*>(&q_s[lane * 4]);

  const float* kbase = past_key + ((size_t)b * SPAST) * H_ + h * HD_;
  const float* knew  = g_qkv + b * (3 * H_) + H_ + h * HD_;

  // ---- scores ----
  for (int s0 = wid * 4; s0 < SEQ; s0 += 32) {
#pragma unroll
    for (int j = 0; j < 4; j++) {
      int s = s0 + j;
      const float* kr = (s < SPAST) ? (kbase + (size_t)s * H_) : knew;
      float4 kv = *reinterpret_cast<const float4*>(kr + lane * 4);
      float d = qv.x * kv.x + qv.y * kv.y + qv.z * kv.z + qv.w * kv.w;
      d += __shfl_xor_sync(0xffffffffu, d, 16);
      d += __shfl_xor_sync(0xffffffffu, d, 8);
      d += __shfl_xor_sync(0xffffffffu, d, 4);
      d += __shfl_xor_sync(0xffffffffu, d, 2);
      d += __shfl_xor_sync(0xffffffffu, d, 1);
      if (lane == 0) sc[s] = d;
    }
  }
  __syncthreads();

  // ---- softmax ----
  float m = -3.0e38f;
  for (int i = t; i < SEQ; i += 256) m = fmaxf(m, sc[i]);
#pragma unroll
  for (int o = 16; o; o >>= 1) m = fmaxf(m, __shfl_xor_sync(0xffffffffu, m, o));
  if (lane == 0) red[wid] = m;
  __syncthreads();
  if (t == 0) {
    float mm = red[0];
    for (int w = 1; w < 8; w++) mm = fmaxf(mm, red[w]);
    red[8] = mm;
  }
  __syncthreads();
  const float gmax = red[8];

  float ls = 0.f;
  for (int i = t; i < SEQ; i += 256) {
    float e = __expf(sc[i] - gmax);
    sc[i] = e;
    ls += e;
  }
#pragma unroll
  for (int o = 16; o; o >>= 1) ls += __shfl_xor_sync(0xffffffffu, ls, o);
  if (lane == 0) red[16 + wid] = ls;
  __syncthreads();
  if (t == 0) {
    float ss = 0.f;
    for (int w = 0; w < 8; w++) ss += red[16 + w];
    red[24] = 1.0f / ss;
  }
  __syncthreads();
  const float inv = red[24];

  // ---- ctx = probs @ V ----
  const float* vbase = past_value + ((size_t)b * SPAST) * H_ + h * HD_;
  const float* vnew  = g_qkv + b * (3 * H_) + 2 * H_ + h * HD_;
  float4 acc = make_float4(0.f, 0.f, 0.f, 0.f);
  for (int i = 0; i < SEQ / 8; i += 4) {
#pragma unroll
    for (int j = 0; j < 4; j++) {
      int s = wid + (i + j) * 8;
      const float* vr = (s < SPAST) ? (vbase + (size_t)s * H_) : vnew;
      float4 vv = *reinterpret_cast<const float4*>(vr + lane * 4);
      float p = sc[s];
      acc.x += p * vv.x;
      acc.y += p * vv.y;
      acc.z += p * vv.z;
      acc.w += p * vv.w;
    }
  }
  *reinterpret_cast<float4*>(&ctxp[wid][lane * 4]) = acc;
  __syncthreads();
  if (t < HD_) {
    float v = 0.f;
#pragma unroll
    for (int w = 0; w < 8; w++) v += ctxp[w][t];
    g_ctx[b * H_ + h * HD_ + t] = v * inv;
  }
}

// ---------------------------------------------------------------------------
extern "C" void kernel_launch(void* const* d_in, const int* in_sizes, int n_in,
                              void* d_out, int out_size) {
  const float* x  = (const float*)d_in[0];   // [32,1,2048]
  const float* pk = (const float*)d_in[1];   // [32,4095,2048]
  const float* pv = (const float*)d_in[2];   // [32,4095,2048]
  const float* Wa = (const float*)d_in[3];   // [2048,6144]
  const float* ba = (const float*)d_in[4];   // [6144]
  const float* Wp = (const float*)d_in[5];   // [2048,2048]
  const float* bp = (const float*)d_in[6];   // [2048]
  float* out = (float*)d_out;                // [32,1,2048] fp32

  float *qkv_part, *qkv, *ctx, *out_part;
  cudaGetSymbolAddress((void**)&qkv_part, g_qkv_part);
  cudaGetSymbolAddress((void**)&qkv, g_qkv);
  cudaGetSymbolAddress((void**)&ctx, g_ctx);
  cudaGetSymbolAddress((void**)&out_part, g_out_part);

  // QKV: N=6144, K=2048 split 8 ways -> 384 blocks
  gemm32_kernel<<<dim3(48, 8), 128>>>(x, Wa, qkv_part, 3 * H_, 2048 / 8);
  reduce_bias_kernel<<<(B_ * 3 * H_ + 255) / 256, 256>>>(qkv_part, ba, qkv, 3 * H_, 8);

  // Attention: one block per (head, batch) -> 512 blocks, all resident in one wave
  attn_kernel<<<dim3(NH_, B_), 256>>>(pk, pv);

  // Proj: N=2048, K=2048 split 16 ways -> 256 blocks
  gemm32_kernel<<<dim3(16, 16), 128>>>(ctx, Wp, out_part, H_, 2048 / 16);
  reduce_bias_kernel<<<(B_ * H_ + 255) / 256, 256>>>(out_part, bp, out, H_, 16);
}

// round 6
// speedup vs baseline: 1.5442x; 1.5442x over previous
#include <cuda_runtime.h>

#define B_    32
#define SPAST 4095
#define SEQ   4096
#define H_    2048
#define NH_   16
#define HD_   128

// Scratch (no allocations allowed) -----------------------------------------
__device__ float g_qkv_part[16 * B_ * 3 * H_];  // QKV k-split partials (16 splits)
__device__ float g_qkv[B_ * 3 * H_];            // reduced qkv [32][6144]
__device__ float g_ctx[B_ * H_];                // attention output [32][2048]
__device__ float g_out_part[32 * B_ * H_];      // proj k-split partials (32 splits)

// ---------------------------------------------------------------------------
// Skinny GEMM, latency-tolerant shape:
//   P[ks][b][n] = sum_{k in segment ks} X[b][k] * W[k][n]
// Block: 256 threads = 8 warps. Warp w covers cols [w*128, (w+1)*128);
// lane owns 4 consecutive cols (one float4 W load, zero redundancy).
// Each thread accumulates 16 batch rows (z-dim picks rows 0-15 / 16-31).
// X chunk staged in smem, consumed as broadcast float4 (1 LDS.128 / 4 k / row).
// Inner 4-k group: 4 LDG.128 + 16 LDS.128 + 128 FFMA -> FFMA-issue dominated;
// unrolled so next group's loads overlap current group's FMA stream.
// Grid: (N/1024, ksplit, 2)
// ---------------------------------------------------------------------------
__global__ __launch_bounds__(256) void gemm_skinny(
    const float* __restrict__ X, const float* __restrict__ W,
    float* __restrict__ P, int N, int kseg) {
  const int t = threadIdx.x;
  const int lane = t & 31;
  const int w = t >> 5;
  const int n0 = blockIdx.x * 1024 + w * 128 + lane * 4;
  const int kbeg = blockIdx.y * kseg;
  const int brow0 = blockIdx.z * 16;

  __shared__ float xs[16][36];  // 36 % 4 == 0 keeps float4 alignment, kills conflicts

  float acc[16][4];
#pragma unroll
  for (int b = 0; b < 16; b++)
#pragma unroll
    for (int c = 0; c < 4; c++) acc[b][c] = 0.f;

  for (int kc = 0; kc < kseg; kc += 32) {
    __syncthreads();
    // stage X chunk: 16 rows x 32 k = 512 floats, coalesced
#pragma unroll
    for (int r = t; r < 512; r += 256) {
      int bb = r >> 5, kk = r & 31;
      xs[bb][kk] = X[(brow0 + bb) * 2048 + kbeg + kc + kk];
    }
    __syncthreads();
#pragma unroll
    for (int kk = 0; kk < 32; kk += 4) {
      const float* wp = W + (size_t)(kbeg + kc + kk) * N + n0;
      float4 w0 = *reinterpret_cast<const float4*>(wp);
      float4 w1 = *reinterpret_cast<const float4*>(wp + N);
      float4 w2 = *reinterpret_cast<const float4*>(wp + 2 * N);
      float4 w3 = *reinterpret_cast<const float4*>(wp + 3 * N);
#pragma unroll
      for (int b = 0; b < 16; b++) {
        float4 x4 = *reinterpret_cast<const float4*>(&xs[b][kk]);
        acc[b][0] += x4.x * w0.x; acc[b][1] += x4.x * w0.y;
        acc[b][2] += x4.x * w0.z; acc[b][3] += x4.x * w0.w;
        acc[b][0] += x4.y * w1.x; acc[b][1] += x4.y * w1.y;
        acc[b][2] += x4.y * w1.z; acc[b][3] += x4.y * w1.w;
        acc[b][0] += x4.z * w2.x; acc[b][1] += x4.z * w2.y;
        acc[b][2] += x4.z * w2.z; acc[b][3] += x4.z * w2.w;
        acc[b][0] += x4.w * w3.x; acc[b][1] += x4.w * w3.y;
        acc[b][2] += x4.w * w3.z; acc[b][3] += x4.w * w3.w;
      }
    }
  }
  float* p = P + (size_t)blockIdx.y * 32 * N;
#pragma unroll
  for (int b = 0; b < 16; b++) {
    float4 v = make_float4(acc[b][0], acc[b][1], acc[b][2], acc[b][3]);
    *reinterpret_cast<float4*>(p + (size_t)(brow0 + b) * N + n0) = v;
  }
}

// out[b][n] = sum_ks P[ks][b][n] + bias[n]
__global__ void reduce_bias_kernel(const float* __restrict__ P,
                                   const float* __restrict__ bias,
                                   float* __restrict__ out, int N, int nsplit) {
  int i = blockIdx.x * 256 + threadIdx.x;
  int total = B_ * N;
  if (i >= total) return;
  float s = bias[i % N];
  for (int k = 0; k < nsplit; k++) s += P[(size_t)k * total + i];
  out[i] = s;
}

// ---------------------------------------------------------------------------
// Decode attention: one block per (b, h). 256 threads = 8 warps.
// 8-deep row unroll in both passes -> 8 independent LDG.128 in flight per warp.
// ---------------------------------------------------------------------------
__global__ __launch_bounds__(256) void attn_kernel(
    const float* __restrict__ past_key, const float* __restrict__ past_value) {
  const int h = blockIdx.x;
  const int b = blockIdx.y;
  const int t = threadIdx.x;
  const int lane = t & 31;
  const int wid = t >> 5;

  __shared__ float q_s[HD_];
  __shared__ float sc[SEQ];       // 16 KB scores
  __shared__ float red[32];
  __shared__ float ctxp[8][HD_];  // 4 KB partial ctx

  const float* qp = g_qkv + b * (3 * H_) + h * HD_;
  if (t < HD_) q_s[t] = qp[t] * 0.08838834764831845f;  // 1/sqrt(128)
  __syncthreads();

  const float4 qv = *reinterpret_cast<const float4*>(&q_s[lane * 4]);

  const float* kbase = past_key + ((size_t)b * SPAST) * H_ + h * HD_;
  const float* knew  = g_qkv + b * (3 * H_) + H_ + h * HD_;

  // ---- scores: warp handles rows wid*8+j, stride 64; MLP=8 ----
  for (int s0 = wid * 8; s0 < SEQ; s0 += 64) {
    float4 kv[8];
#pragma unroll
    for (int j = 0; j < 8; j++) {
      int s = s0 + j;
      const float* kr = (s < SPAST) ? (kbase + (size_t)s * H_) : knew;
      kv[j] = *reinterpret_cast<const float4*>(kr + lane * 4);
    }
#pragma unroll
    for (int j = 0; j < 8; j++) {
      float d = qv.x * kv[j].x + qv.y * kv[j].y + qv.z * kv[j].z + qv.w * kv[j].w;
      d += __shfl_xor_sync(0xffffffffu, d, 16);
      d += __shfl_xor_sync(0xffffffffu, d, 8);
      d += __shfl_xor_sync(0xffffffffu, d, 4);
      d += __shfl_xor_sync(0xffffffffu, d, 2);
      d += __shfl_xor_sync(0xffffffffu, d, 1);
      if (lane == 0) sc[s0 + j] = d;
    }
  }
  __syncthreads();

  // ---- softmax over sc[0..4095] ----
  float m = -3.0e38f;
  for (int i = t; i < SEQ; i += 256) m = fmaxf(m, sc[i]);
#pragma unroll
  for (int o = 16; o; o >>= 1) m = fmaxf(m, __shfl_xor_sync(0xffffffffu, m, o));
  if (lane == 0) red[wid] = m;
  __syncthreads();
  if (t == 0) {
    float mm = red[0];
    for (int ww = 1; ww < 8; ww++) mm = fmaxf(mm, red[ww]);
    red[8] = mm;
  }
  __syncthreads();
  const float gmax = red[8];

  float ls = 0.f;
  for (int i = t; i < SEQ; i += 256) {
    float e = __expf(sc[i] - gmax);
    sc[i] = e;
    ls += e;
  }
#pragma unroll
  for (int o = 16; o; o >>= 1) ls += __shfl_xor_sync(0xffffffffu, ls, o);
  if (lane == 0) red[16 + wid] = ls;
  __syncthreads();
  if (t == 0) {
    float ss = 0.f;
    for (int ww = 0; ww < 8; ww++) ss += red[16 + ww];
    red[24] = 1.0f / ss;
  }
  __syncthreads();
  const float inv = red[24];

  // ---- ctx = probs @ V, rows wid + 8*i, unroll 8 -> MLP=8 ----
  const float* vbase = past_value + ((size_t)b * SPAST) * H_ + h * HD_;
  const float* vnew  = g_qkv + b * (3 * H_) + 2 * H_ + h * HD_;
  float4 acc = make_float4(0.f, 0.f, 0.f, 0.f);
  for (int i = 0; i < SEQ / 8; i += 8) {
    float4 vv[8];
    float p[8];
#pragma unroll
    for (int j = 0; j < 8; j++) {
      int s = wid + (i + j) * 8;
      const float* vr = (s < SPAST) ? (vbase + (size_t)s * H_) : vnew;
      vv[j] = *reinterpret_cast<const float4*>(vr + lane * 4);
      p[j] = sc[s];
    }
#pragma unroll
    for (int j = 0; j < 8; j++) {
      acc.x += p[j] * vv[j].x;
      acc.y += p[j] * vv[j].y;
      acc.z += p[j] * vv[j].z;
      acc.w += p[j] * vv[j].w;
    }
  }
  *reinterpret_cast<float4*>(&ctxp[wid][lane * 4]) = acc;
  __syncthreads();
  if (t < HD_) {
    float v = 0.f;
#pragma unroll
    for (int ww = 0; ww < 8; ww++) v += ctxp[ww][t];
    g_ctx[b * H_ + h * HD_ + t] = v * inv;
  }
}

// ---------------------------------------------------------------------------
extern "C" void kernel_launch(void* const* d_in, const int* in_sizes, int n_in,
                              void* d_out, int out_size) {
  const float* x  = (const float*)d_in[0];   // [32,1,2048]
  const float* pk = (const float*)d_in[1];   // [32,4095,2048]
  const float* pv = (const float*)d_in[2];   // [32,4095,2048]
  const float* Wa = (const float*)d_in[3];   // [2048,6144]
  const float* ba = (const float*)d_in[4];   // [6144]
  const float* Wp = (const float*)d_in[5];   // [2048,2048]
  const float* bp = (const float*)d_in[6];   // [2048]
  float* out = (float*)d_out;                // [32,1,2048] fp32

  float *qkv_part, *qkv, *ctx, *out_part;
  cudaGetSymbolAddress((void**)&qkv_part, g_qkv_part);
  cudaGetSymbolAddress((void**)&qkv, g_qkv);
  cudaGetSymbolAddress((void**)&ctx, g_ctx);
  cudaGetSymbolAddress((void**)&out_part, g_out_part);

  // QKV: N=6144 -> 6 n-blocks, K split 16 (kseg=128), batch split 2 -> 192 blocks
  gemm_skinny<<<dim3(6, 16, 2), 256>>>(x, Wa, qkv_part, 3 * H_, 2048 / 16);
  reduce_bias_kernel<<<(B_ * 3 * H_ + 255) / 256, 256>>>(qkv_part, ba, qkv, 3 * H_, 16);

  // Attention: one block per (head, batch) -> 512 blocks, single wave
  attn_kernel<<<dim3(NH_, B_), 256>>>(pk, pv);

  // Proj: N=2048 -> 2 n-blocks, K split 32 (kseg=64), batch split 2 -> 128 blocks
  gemm_skinny<<<dim3(2, 32, 2), 256>>>(ctx, Wp, out_part, H_, 2048 / 32);
  reduce_bias_kernel<<<(B_ * H_ + 255) / 256, 256>>>(out_part, bp, out, H_, 32);
}